// round 11
// baseline (speedup 1.0000x reference)
#include <cuda_runtime.h>
#include <mma.h>
#include <math.h>
#include <stdint.h>

#define NROWS 8192
#define DIM 512

__device__ float g_Q [NROWS*DIM];
__device__ float g_K [NROWS*DIM];
__device__ float g_V [NROWS*DIM];
__device__ float g_XR[NROWS*DIM];
__device__ float g_H [NROWS*DIM];

__device__ __forceinline__ float tf32r(float v) { return nvcuda::wmma::__float_to_tf32(v); }

__device__ __forceinline__ void mma8(float* c, const float* a, const float* b) {
    asm volatile("mma.sync.aligned.m16n8k8.row.col.f32.tf32.tf32.f32 "
        "{%0,%1,%2,%3}, {%4,%5,%6,%7}, {%8,%9}, {%0,%1,%2,%3};"
        : "+f"(c[0]), "+f"(c[1]), "+f"(c[2]), "+f"(c[3])
        : "r"(__float_as_uint(a[0])), "r"(__float_as_uint(a[1])),
          "r"(__float_as_uint(a[2])), "r"(__float_as_uint(a[3])),
          "r"(__float_as_uint(b[0])), "r"(__float_as_uint(b[1])));
}

__device__ __forceinline__ void cpa16(uint32_t dst, const void* src) {
    asm volatile("cp.async.cg.shared.global [%0], [%1], 16;" :: "r"(dst), "l"(src));
}
#define CPA_COMMIT() asm volatile("cp.async.commit_group;" ::: "memory")
#define CPA_WAIT0()  asm volatile("cp.async.wait_group 0;"  ::: "memory")
#define CPA_WAIT1()  asm volatile("cp.async.wait_group 1;"  ::: "memory")
#define CPA_WAIT2()  asm volatile("cp.async.wait_group 2;"  ::: "memory")

// ===========================================================================
// Retention: O = (D .* (Q K^T)) @ V.  CTA = 64 Q-rows, 512 thr (16 warps).
// j-chunk 256.
//   QK: S 64x256, warp grid 2x8, tile 32x32, 32-col K stages, 3-slot ring,
//       D tile folded into stage groups (lands in Ds during QK).
//   D-phase: Ss = tf32(S .* D), PAIR-INTERLEAVED: S column (within 8-group)
//       c<4 at pos 2c, c>=4 at pos 2(c-4)+1 -> (qc, qc+4) adjacent = LDS.64.
//       Row stride 264 (=8 mod 32): conflict-free per half-warp LDS.64 phase.
//   SV: O 64x512, warp grid 2x8, tile 32x64. 16-row V stages, 4-slot ring
//       (slots 0,1 in ring tail after Ssp, slots 2,3 overlay Ds), 16 stages,
//       stages 0/1 pre-issued around the D-phase.
// SMEM: ring 3*11520 = 34560 fl; after QK it is re-used as
//       Ssp[64*264]=16896 fl + vslot0 (16896..25215) + vslot1 (25216..33535).
//       region2 = 16640 fl (Ds[64][260] / vslot2,3).  51200 fl = 204800 B.
// ===========================================================================
#define STG_FL   11520
#define RING_FL  (3*STG_FL)
#define REG2_FL  16640
#define VSLOT_FL 8320               // 16 rows x 520
#define SSP_FL   (64*264)           // 16896
#define RET_SMEM ((RING_FL + REG2_FL) * 4)

__global__ void __launch_bounds__(512, 1) retention_mma(
    const float* __restrict__ Q, const float* __restrict__ K,
    const float* __restrict__ V, const float* __restrict__ D,
    float* __restrict__ O)
{
    extern __shared__ float sm[];
    float* ring = sm;
    float* Ssp  = sm;                                  // paired S, 64 x 264
    float (*Ds)[260] = (float(*)[260])(sm + RING_FL);

    float* vslot[4] = { sm + SSP_FL, sm + SSP_FL + VSLOT_FL,
                        sm + RING_FL, sm + RING_FL + VSLOT_FL };

    const int tid = threadIdx.x;
    const int lane = tid & 31, w = tid >> 5;
    const int wm = w >> 3, wn = w & 7;       // 2 x 8 warp grid
    const int qr = lane >> 2, qc = lane & 3;
    const int i0 = blockIdx.x * 64;

    const uint32_t sRing = (uint32_t)__cvta_generic_to_shared(ring);
    const uint32_t sDs   = (uint32_t)__cvta_generic_to_shared(sm + RING_FL);
    uint32_t sV[4];
    #pragma unroll
    for (int i = 0; i < 4; i++)
        sV[i] = (uint32_t)__cvta_generic_to_shared(vslot[i]);

    // loader indices
    const int lq_r = tid >> 3,  lq_c = (tid & 7) * 4;     // Q: 64 rows
    const int lk_r = tid >> 3,  lk_c = (tid & 7) * 4;     // K: 4 x 64 rows
    const int lv_r = tid >> 7,  lv_c = (tid & 127) * 4;   // V: 4 passes of 4 rows
    const int ld_r = tid >> 6,  ld_c = (tid & 63) * 4;    // D (tid<256)

    const int spos = ((2*qc) & 3) * 2 + (qc >> 1);        // paired position base

    float o[2][8][4];
    #pragma unroll
    for (int f = 0; f < 2; f++)
        #pragma unroll
        for (int g = 0; g < 8; g++)
            #pragma unroll
            for (int e = 0; e < 4; e++) o[f][g][e] = 0.f;

    #pragma unroll 1
    for (int j0 = 0; j0 < NROWS; j0 += 256) {
        // ---- QK stage issue (stage kc -> ring slot kc%3; carries D rows) ----
        auto issue_qk = [&](int kc) {
            uint32_t b = sRing + (uint32_t)((kc % 3) * STG_FL) * 4u;
            cpa16(b + (uint32_t)(lq_r*36 + lq_c)*4u,
                  &Q[(size_t)(i0 + lq_r)*DIM + kc*32 + lq_c]);
            #pragma unroll
            for (int p = 0; p < 4; p++) {
                int r = lk_r + p*64;
                cpa16(b + (uint32_t)(2304 + r*36 + lk_c)*4u,
                      &K[(size_t)(j0 + r)*DIM + kc*32 + lk_c]);
            }
            if (tid < 256) {
                int dr = kc*4 + ld_r;
                cpa16(sDs + (uint32_t)(dr*260 + ld_c)*4u,
                      &D[(size_t)(i0 + dr)*NROWS + j0 + ld_c]);
            }
            CPA_COMMIT();
        };

        issue_qk(0);
        issue_qk(1);

        float s[2][4][4];
        #pragma unroll
        for (int f = 0; f < 2; f++)
            #pragma unroll
            for (int g = 0; g < 4; g++)
                #pragma unroll
                for (int e = 0; e < 4; e++) s[f][g][e] = 0.f;

        // ---------------- QK:  S = Q @ K[j0:j0+256]^T ----------------
        #pragma unroll 1
        for (int kc = 0; kc < 16; kc++) {
            if (kc < 15) { CPA_WAIT1(); } else { CPA_WAIT0(); }
            __syncthreads();
            if (kc < 14) issue_qk(kc + 2);
            const float* Qs = ring + (kc % 3) * STG_FL;
            const float* Ks = Qs + 2304;
            #pragma unroll
            for (int k8 = 0; k8 < 4; k8++) {
                const int kk = k8*8 + qc;
                float a[2][4];
                #pragma unroll
                for (int f = 0; f < 2; f++) {
                    int rb = wm*32 + f*16 + qr;
                    a[f][0] = Qs[rb*36 + kk];       a[f][1] = Qs[(rb+8)*36 + kk];
                    a[f][2] = Qs[rb*36 + kk + 4];   a[f][3] = Qs[(rb+8)*36 + kk + 4];
                }
                #pragma unroll
                for (int g = 0; g < 4; g++) {
                    int nb = wn*32 + g*8 + qr;
                    float b[2] = { Ks[nb*36 + kk], Ks[nb*36 + kk + 4] };
                    mma8(s[0][g], a[0], b);
                    mma8(s[1][g], a[1], b);
                }
            }
        }
        __syncthreads();   // QK reads done -> Ssp / vslot0,1 (alias ring) usable

        // ---- SV stage issue (stage st -> vslot st%4, 16 V-rows) ----
        auto issue_v = [&](int st) {
            uint32_t b = sV[st & 3];
            #pragma unroll
            for (int p = 0; p < 4; p++) {
                int r = lv_r + p*4;
                cpa16(b + (uint32_t)(r*520 + lv_c)*4u,
                      &V[(size_t)(j0 + st*16 + r)*DIM + lv_c]);
            }
            CPA_COMMIT();
        };

        // pre-issue V stages 0,1 into ring-tail slots; overlap with D-phase
        issue_v(0);
        issue_v(1);

        // ------- D-phase: Ssp = tf32(S .* Ds), pair-interleaved writes -------
        #pragma unroll
        for (int f = 0; f < 2; f++)
            #pragma unroll
            for (int g = 0; g < 4; g++) {
                int r = wm*32 + f*16 + qr;
                int c = wn*32 + g*8 + 2*qc;
                int G8 = (wn*4 + g)*8;
                float2 d0 = *(float2*)&Ds[r][c];
                float2 d1 = *(float2*)&Ds[r+8][c];
                Ssp[r*264 + G8 + spos]         = tf32r(s[f][g][0]*d0.x);
                Ssp[r*264 + G8 + spos + 2]     = tf32r(s[f][g][1]*d0.y);
                Ssp[(r+8)*264 + G8 + spos]     = tf32r(s[f][g][2]*d1.x);
                Ssp[(r+8)*264 + G8 + spos + 2] = tf32r(s[f][g][3]*d1.y);
            }
        __syncthreads();   // Ds reads done -> vslot2,3 (alias Ds) usable

        issue_v(2);

        // ------------- SV:  O += Ssp @ V[j0:j0+256]  (16 stages) -------------
        #pragma unroll 1
        for (int st = 0; st < 16; st++) {
            if (st < 14) { CPA_WAIT2(); }
            else if (st < 15) { CPA_WAIT1(); }
            else { CPA_WAIT0(); }
            __syncthreads();
            if (st + 3 < 16) issue_v(st + 3);
            const float* Vb = vslot[st & 3];
            #pragma unroll
            for (int sub = 0; sub < 2; sub++) {
                const int G8 = (st*2 + sub)*8;
                float a[2][4];
                #pragma unroll
                for (int f = 0; f < 2; f++) {
                    int rb = wm*32 + f*16 + qr;
                    float2 p0 = *(const float2*)&Ssp[rb*264 + G8 + 2*qc];
                    float2 p1 = *(const float2*)&Ssp[(rb+8)*264 + G8 + 2*qc];
                    a[f][0] = p0.x; a[f][1] = p1.x; a[f][2] = p0.y; a[f][3] = p1.y;
                }
                const float* v0 = Vb + (sub*8 + qc)*520;
                const float* v1 = Vb + (sub*8 + qc + 4)*520;
                #pragma unroll
                for (int g = 0; g < 8; g++) {
                    int n = wn*64 + g*8 + qr;
                    float b[2] = { v0[n], v1[n] };
                    mma8(o[0][g], a[0], b);
                    mma8(o[1][g], a[1], b);
                }
            }
        }
        __syncthreads();   // all Ssp/V reads done before next chunk's issues
    }

    // ---------------- epilogue ----------------
    #pragma unroll
    for (int f = 0; f < 2; f++)
        #pragma unroll
        for (int g = 0; g < 8; g++) {
            int r = i0 + wm*32 + f*16 + qr;
            int c = wn*64 + g*8 + 2*qc;
            *(float2*)&O[(size_t)r*DIM + c]       = make_float2(o[f][g][0], o[f][g][1]);
            *(float2*)&O[(size_t)(r + 8)*DIM + c] = make_float2(o[f][g][2], o[f][g][3]);
        }
}

// ===========================================================================
// Small GEMMs (tf32x3): C = act(A @ B + bias).  BM=128, BN=64, BK=32.
// ===========================================================================
#define GEMM_SMEM 55296

template<int ACT, int ROUND>
__global__ void __launch_bounds__(256) gemm_x3(
    const float* __restrict__ A, const float* __restrict__ B,
    const float* __restrict__ bias, float* __restrict__ C)
{
    extern __shared__ float sm[];
    float (*Ah)[36] = (float(*)[36]) sm;
    float (*Al)[36] = (float(*)[36])(sm + 4608);
    float (*Bh)[72] = (float(*)[72])(sm + 9216);
    float (*Bl)[72] = (float(*)[72])(sm + 11520);

    const int tid = threadIdx.x;
    const int lane = tid & 31, w = tid >> 5;
    const int wm = w >> 1, wn = w & 1;
    const int qr = lane >> 2, qc = lane & 3;
    const int bm = blockIdx.x * 128, bn = blockIdx.y * 64;

    float acc[2][4][4];
    #pragma unroll
    for (int f = 0; f < 2; f++)
        #pragma unroll
        for (int g = 0; g < 4; g++)
            #pragma unroll
            for (int e = 0; e < 4; e++) acc[f][g][e] = 0.f;

    float4 ap[4]; float4 bp[2];
    #pragma unroll
    for (int p = 0; p < 4; p++) {
        int idx = tid + p*256, r = idx >> 3, c4 = (idx & 7) * 4;
        ap[p] = *(const float4*)&A[(size_t)(bm + r)*DIM + c4];
    }
    #pragma unroll
    for (int p = 0; p < 2; p++) {
        int idx = tid + p*256, r = idx >> 4, c4 = (idx & 15) * 4;
        bp[p] = *(const float4*)&B[(size_t)r*DIM + bn + c4];
    }

    #pragma unroll 1
    for (int kc = 0; kc < 16; kc++) {
        #pragma unroll
        for (int p = 0; p < 4; p++) {
            int idx = tid + p*256, r = idx >> 3, c4 = (idx & 7) * 4;
            float vv[4] = {ap[p].x, ap[p].y, ap[p].z, ap[p].w};
            #pragma unroll
            for (int e = 0; e < 4; e++) {
                float h = tf32r(vv[e]);
                Ah[r][c4+e] = h;
                Al[r][c4+e] = tf32r(vv[e] - h);
            }
        }
        #pragma unroll
        for (int p = 0; p < 2; p++) {
            int idx = tid + p*256, r = idx >> 4, c4 = (idx & 15) * 4;
            float vv[4] = {bp[p].x, bp[p].y, bp[p].z, bp[p].w};
            #pragma unroll
            for (int e = 0; e < 4; e++) {
                float h = tf32r(vv[e]);
                Bh[r][c4+e] = h;
                Bl[r][c4+e] = tf32r(vv[e] - h);
            }
        }
        __syncthreads();
        if (kc < 15) {
            #pragma unroll
            for (int p = 0; p < 4; p++) {
                int idx = tid + p*256, r = idx >> 3, c4 = (idx & 7) * 4;
                ap[p] = *(const float4*)&A[(size_t)(bm + r)*DIM + (kc+1)*32 + c4];
            }
            #pragma unroll
            for (int p = 0; p < 2; p++) {
                int idx = tid + p*256, r = idx >> 4, c4 = (idx & 15) * 4;
                bp[p] = *(const float4*)&B[(size_t)((kc+1)*32 + r)*DIM + bn + c4];
            }
        }
        #pragma unroll
        for (int k8 = 0; k8 < 4; k8++) {
            const int kk = k8*8 + qc;
            float ah[2][4], al[2][4];
            #pragma unroll
            for (int f = 0; f < 2; f++) {
                int rb = wm*32 + f*16 + qr;
                ah[f][0] = Ah[rb][kk];   ah[f][1] = Ah[rb+8][kk];
                ah[f][2] = Ah[rb][kk+4]; ah[f][3] = Ah[rb+8][kk+4];
                al[f][0] = Al[rb][kk];   al[f][1] = Al[rb+8][kk];
                al[f][2] = Al[rb][kk+4]; al[f][3] = Al[rb+8][kk+4];
            }
            #pragma unroll
            for (int g = 0; g < 4; g++) {
                int n = wn*32 + g*8 + qr;
                float bh[2] = { Bh[kk][n], Bh[kk+4][n] };
                float bl[2] = { Bl[kk][n], Bl[kk+4][n] };
                #pragma unroll
                for (int f = 0; f < 2; f++) {
                    mma8(acc[f][g], ah[f], bh);
                    mma8(acc[f][g], al[f], bh);
                    mma8(acc[f][g], ah[f], bl);
                }
            }
        }
        __syncthreads();
    }

    #pragma unroll
    for (int f = 0; f < 2; f++)
        #pragma unroll
        for (int g = 0; g < 4; g++) {
            int r = bm + wm*32 + f*16 + qr;
            int c = bn + wn*32 + g*8 + 2*qc;
            float2 bb = *(const float2*)&bias[c];
            float v0 = acc[f][g][0] + bb.x, v1 = acc[f][g][1] + bb.y;
            float v2 = acc[f][g][2] + bb.x, v3 = acc[f][g][3] + bb.y;
            if (ACT == 1) {
                v0 = 0.5f*v0*(1.f + erff(v0*0.70710678118654752f));
                v1 = 0.5f*v1*(1.f + erff(v1*0.70710678118654752f));
                v2 = 0.5f*v2*(1.f + erff(v2*0.70710678118654752f));
                v3 = 0.5f*v3*(1.f + erff(v3*0.70710678118654752f));
            }
            if (ROUND == 1) { v0 = tf32r(v0); v1 = tf32r(v1); v2 = tf32r(v2); v3 = tf32r(v3); }
            *(float2*)&C[(size_t)r*DIM + c]       = make_float2(v0, v1);
            *(float2*)&C[(size_t)(r + 8)*DIM + c] = make_float2(v2, v3);
        }
}

// ---------------------------------------------------------------------------
__global__ void groupnorm_kernel(float* __restrict__ out,
                                 const float* __restrict__ gamma,
                                 const float* __restrict__ beta)
{
    __shared__ float buf[512];
    __shared__ float smu[16], siv[16];
    const int row = blockIdx.x;
    const int tid = threadIdx.x;
    float* p = out + (size_t)row * DIM;
    buf[tid]       = p[tid];
    buf[tid + 256] = p[tid + 256];
    __syncthreads();
    if (tid < 16) {
        float sx = 0.f, s2 = 0.f;
        #pragma unroll
        for (int c = 0; c < 32; c++) { float v = buf[tid*32 + c]; sx += v; s2 += v*v; }
        float mu  = sx * (1.f/32.f);
        float var = s2 * (1.f/32.f) - mu*mu;
        smu[tid] = mu;
        siv[tid] = rsqrtf(var + 1e-5f);
    }
    __syncthreads();
    #pragma unroll
    for (int q = 0; q < 2; q++) {
        int c = tid + q*256;
        int g = c >> 5;
        p[c] = (buf[c] - smu[g]) * siv[g] * gamma[c] + beta[c];
    }
}

// ---------------------------------------------------------------------------
extern "C" void kernel_launch(void* const* d_in, const int* in_sizes, int n_in,
                              void* d_out, int out_size)
{
    const float* x     = (const float*)d_in[0];
    const float* D     = (const float*)d_in[1];
    const float* Wq    = (const float*)d_in[2];
    const float* bq    = (const float*)d_in[3];
    const float* Wk    = (const float*)d_in[4];
    const float* bk    = (const float*)d_in[5];
    const float* Wv    = (const float*)d_in[6];
    const float* bv    = (const float*)d_in[7];
    const float* Wf    = (const float*)d_in[8];
    const float* bf    = (const float*)d_in[9];
    const float* Wp    = (const float*)d_in[10];
    const float* bp    = (const float*)d_in[11];
    const float* gamma = (const float*)d_in[12];
    const float* beta  = (const float*)d_in[13];
    float* out = (float*)d_out;

    float *Q, *K, *V, *XR, *H;
    cudaGetSymbolAddress((void**)&Q,  g_Q);
    cudaGetSymbolAddress((void**)&K,  g_K);
    cudaGetSymbolAddress((void**)&V,  g_V);
    cudaGetSymbolAddress((void**)&XR, g_XR);
    cudaGetSymbolAddress((void**)&H,  g_H);

    cudaFuncSetAttribute(gemm_x3<0,1>,
                         cudaFuncAttributeMaxDynamicSharedMemorySize, GEMM_SMEM);
    cudaFuncSetAttribute(gemm_x3<1,0>,
                         cudaFuncAttributeMaxDynamicSharedMemorySize, GEMM_SMEM);
    cudaFuncSetAttribute(gemm_x3<0,0>,
                         cudaFuncAttributeMaxDynamicSharedMemorySize, GEMM_SMEM);
    cudaFuncSetAttribute(retention_mma,
                         cudaFuncAttributeMaxDynamicSharedMemorySize, RET_SMEM);

    dim3 gs(NROWS/128, DIM/64);    // 64 x 8
    gemm_x3<0,1><<<gs, 256, GEMM_SMEM>>>(x, Wq, bq, Q);
    gemm_x3<0,1><<<gs, 256, GEMM_SMEM>>>(x, Wk, bk, K);
    gemm_x3<0,1><<<gs, 256, GEMM_SMEM>>>(x, Wv, bv, V);

    retention_mma<<<NROWS/64, 512, RET_SMEM>>>(Q, K, V, D, XR);

    gemm_x3<1,0><<<gs, 256, GEMM_SMEM>>>(XR, Wf, bf, H);   // exact GELU
    gemm_x3<0,0><<<gs, 256, GEMM_SMEM>>>(H,  Wp, bp, out);

    groupnorm_kernel<<<NROWS, 256>>>(out, gamma, beta);
}

// round 12
// speedup vs baseline: 1.1522x; 1.1522x over previous
#include <cuda_runtime.h>
#include <mma.h>
#include <math.h>
#include <stdint.h>

#define NROWS 8192
#define DIM 512

__device__ float g_Q [NROWS*DIM];
__device__ float g_K [NROWS*DIM];
__device__ float g_V [NROWS*DIM];
__device__ float g_XR[NROWS*DIM];
__device__ float g_H [NROWS*DIM];

__device__ __forceinline__ float tf32r(float v) { return nvcuda::wmma::__float_to_tf32(v); }

__device__ __forceinline__ void mma8(float* c, const float* a, const float* b) {
    asm volatile("mma.sync.aligned.m16n8k8.row.col.f32.tf32.tf32.f32 "
        "{%0,%1,%2,%3}, {%4,%5,%6,%7}, {%8,%9}, {%0,%1,%2,%3};"
        : "+f"(c[0]), "+f"(c[1]), "+f"(c[2]), "+f"(c[3])
        : "r"(__float_as_uint(a[0])), "r"(__float_as_uint(a[1])),
          "r"(__float_as_uint(a[2])), "r"(__float_as_uint(a[3])),
          "r"(__float_as_uint(b[0])), "r"(__float_as_uint(b[1])));
}

__device__ __forceinline__ void cpa16(uint32_t dst, const void* src) {
    asm volatile("cp.async.cg.shared.global [%0], [%1], 16;" :: "r"(dst), "l"(src));
}
#define CPA_COMMIT() asm volatile("cp.async.commit_group;" ::: "memory")
#define CPA_WAIT0()  asm volatile("cp.async.wait_group 0;"  ::: "memory")
#define CPA_WAIT1()  asm volatile("cp.async.wait_group 1;"  ::: "memory")
#define CPA_WAIT2()  asm volatile("cp.async.wait_group 2;"  ::: "memory")

// ===========================================================================
// Retention: O = (D .* (Q K^T)) @ V.  CTA = 64 Q-rows, 512 thr (16 warps).
// j-chunk 256.  Q and K arrive in gmem with PAIR-INTERLEAVED columns within
// each 8-group (col m -> 2m for m<4, 2(m-4)+1 for m>=4), so (k, k+4) are
// adjacent: QK A and B fragments load as LDS.64.  Row stride 40 in stages
// (8 mod 32 -> conflict-free LDS.64 per half-warp phase).
//   QK: S 64x256, warp grid 2x8, tile 32x32, 32-col stages, 3-slot ring,
//       D tile folded into stage cp.async groups.
//   D-phase: Ssp = tf32(S .* D), pair-interleaved (stride 264).
//   SV: O 64x512, warp grid 2x8, tile 32x64, 16-row V stages, 4-slot ring.
// SMEM: ring 3*12800 = 38400 fl (after QK: Ssp 16896 + vslot0/1 = 33536
//       alias it) + region2 16640 fl (Ds / vslot2,3) = 55040 fl = 220160 B.
// ===========================================================================
#define STG_FL   12800              // Q 64x40 + K 256x40
#define RING_FL  (3*STG_FL)         // 38400
#define REG2_FL  16640
#define VSLOT_FL 8320               // 16 rows x 520
#define SSP_FL   (64*264)           // 16896
#define RET_SMEM ((RING_FL + REG2_FL) * 4)   // 220160

__global__ void __launch_bounds__(512, 1) retention_mma(
    const float* __restrict__ Q, const float* __restrict__ K,
    const float* __restrict__ V, const float* __restrict__ D,
    float* __restrict__ O)
{
    extern __shared__ float sm[];
    float* ring = sm;
    float* Ssp  = sm;                                  // paired S, 64 x 264
    float (*Ds)[260] = (float(*)[260])(sm + RING_FL);

    float* vslot[4] = { sm + SSP_FL, sm + SSP_FL + VSLOT_FL,
                        sm + RING_FL, sm + RING_FL + VSLOT_FL };

    const int tid = threadIdx.x;
    const int lane = tid & 31, w = tid >> 5;
    const int wm = w >> 3, wn = w & 7;       // 2 x 8 warp grid
    const int qr = lane >> 2, qc = lane & 3;
    const int i0 = blockIdx.x * 64;

    const uint32_t sRing = (uint32_t)__cvta_generic_to_shared(ring);
    const uint32_t sDs   = (uint32_t)__cvta_generic_to_shared(sm + RING_FL);
    uint32_t sV[4];
    #pragma unroll
    for (int i = 0; i < 4; i++)
        sV[i] = (uint32_t)__cvta_generic_to_shared(vslot[i]);

    // loader indices
    const int lq_r = tid >> 3,  lq_c = (tid & 7) * 4;     // Q: 64 rows, 1 ld/thr
    const int lk_r = tid >> 3,  lk_c = (tid & 7) * 4;     // K: 4 x 64 rows
    const int lv_r = tid >> 7,  lv_c = (tid & 127) * 4;   // V: 4 passes of 4 rows
    const int ld_r = tid >> 6,  ld_c = (tid & 63) * 4;    // D (tid<256)

    const int spos = ((2*qc) & 3) * 2 + (qc >> 1);        // Ssp paired pos base

    float o[2][8][4];
    #pragma unroll
    for (int f = 0; f < 2; f++)
        #pragma unroll
        for (int g = 0; g < 8; g++)
            #pragma unroll
            for (int e = 0; e < 4; e++) o[f][g][e] = 0.f;

    #pragma unroll 1
    for (int j0 = 0; j0 < NROWS; j0 += 256) {
        // ---- QK stage issue (stage kc -> ring slot kc%3; carries D rows) ----
        auto issue_qk = [&](int kc) {
            uint32_t b = sRing + (uint32_t)((kc % 3) * STG_FL) * 4u;
            cpa16(b + (uint32_t)(lq_r*40 + lq_c)*4u,
                  &Q[(size_t)(i0 + lq_r)*DIM + kc*32 + lq_c]);
            #pragma unroll
            for (int p = 0; p < 4; p++) {
                int r = lk_r + p*64;
                cpa16(b + (uint32_t)(2560 + r*40 + lk_c)*4u,
                      &K[(size_t)(j0 + r)*DIM + kc*32 + lk_c]);
            }
            if (tid < 256) {
                int dr = kc*4 + ld_r;
                cpa16(sDs + (uint32_t)(dr*260 + ld_c)*4u,
                      &D[(size_t)(i0 + dr)*NROWS + j0 + ld_c]);
            }
            CPA_COMMIT();
        };

        issue_qk(0);
        issue_qk(1);

        float s[2][4][4];
        #pragma unroll
        for (int f = 0; f < 2; f++)
            #pragma unroll
            for (int g = 0; g < 4; g++)
                #pragma unroll
                for (int e = 0; e < 4; e++) s[f][g][e] = 0.f;

        // ---------------- QK:  S = Q @ K[j0:j0+256]^T ----------------
        #pragma unroll 1
        for (int kc = 0; kc < 16; kc++) {
            if (kc < 15) { CPA_WAIT1(); } else { CPA_WAIT0(); }
            __syncthreads();
            if (kc < 14) issue_qk(kc + 2);
            const float* Qs = ring + (kc % 3) * STG_FL;
            const float* Ks = Qs + 2560;
            #pragma unroll
            for (int k8 = 0; k8 < 4; k8++) {
                const int kp = k8*8 + 2*qc;     // paired (k, k+4) offset
                float a[2][4];
                #pragma unroll
                for (int f = 0; f < 2; f++) {
                    int rb = wm*32 + f*16 + qr;
                    float2 a0 = *(const float2*)&Qs[rb*40 + kp];
                    float2 a1 = *(const float2*)&Qs[(rb+8)*40 + kp];
                    a[f][0] = a0.x; a[f][1] = a1.x; a[f][2] = a0.y; a[f][3] = a1.y;
                }
                #pragma unroll
                for (int g = 0; g < 4; g++) {
                    int nb = wn*32 + g*8 + qr;
                    float2 bb = *(const float2*)&Ks[nb*40 + kp];
                    float b[2] = { bb.x, bb.y };
                    mma8(s[0][g], a[0], b);
                    mma8(s[1][g], a[1], b);
                }
            }
        }
        __syncthreads();   // QK reads done -> Ssp / vslot0,1 (alias ring) usable

        // ---- SV stage issue (stage st -> vslot st%4, 16 V-rows) ----
        auto issue_v = [&](int st) {
            uint32_t b = sV[st & 3];
            #pragma unroll
            for (int p = 0; p < 4; p++) {
                int r = lv_r + p*4;
                cpa16(b + (uint32_t)(r*520 + lv_c)*4u,
                      &V[(size_t)(j0 + st*16 + r)*DIM + lv_c]);
            }
            CPA_COMMIT();
        };

        issue_v(0);
        issue_v(1);

        // ------- D-phase: Ssp = tf32(S .* Ds), pair-interleaved writes -------
        #pragma unroll
        for (int f = 0; f < 2; f++)
            #pragma unroll
            for (int g = 0; g < 4; g++) {
                int r = wm*32 + f*16 + qr;
                int c = wn*32 + g*8 + 2*qc;
                int G8 = (wn*4 + g)*8;
                float2 d0 = *(float2*)&Ds[r][c];
                float2 d1 = *(float2*)&Ds[r+8][c];
                Ssp[r*264 + G8 + spos]         = tf32r(s[f][g][0]*d0.x);
                Ssp[r*264 + G8 + spos + 2]     = tf32r(s[f][g][1]*d0.y);
                Ssp[(r+8)*264 + G8 + spos]     = tf32r(s[f][g][2]*d1.x);
                Ssp[(r+8)*264 + G8 + spos + 2] = tf32r(s[f][g][3]*d1.y);
            }
        __syncthreads();   // Ds reads done -> vslot2,3 (alias Ds) usable

        issue_v(2);

        // ------------- SV:  O += Ssp @ V[j0:j0+256]  (16 stages) -------------
        #pragma unroll 1
        for (int st = 0; st < 16; st++) {
            if (st < 14) { CPA_WAIT2(); }
            else if (st < 15) { CPA_WAIT1(); }
            else { CPA_WAIT0(); }
            __syncthreads();
            if (st + 3 < 16) issue_v(st + 3);
            const float* Vb = vslot[st & 3];
            #pragma unroll
            for (int sub = 0; sub < 2; sub++) {
                const int G8 = (st*2 + sub)*8;
                float a[2][4];
                #pragma unroll
                for (int f = 0; f < 2; f++) {
                    int rb = wm*32 + f*16 + qr;
                    float2 p0 = *(const float2*)&Ssp[rb*264 + G8 + 2*qc];
                    float2 p1 = *(const float2*)&Ssp[(rb+8)*264 + G8 + 2*qc];
                    a[f][0] = p0.x; a[f][1] = p1.x; a[f][2] = p0.y; a[f][3] = p1.y;
                }
                const float* v0 = Vb + (sub*8 + qc)*520;
                const float* v1 = Vb + (sub*8 + qc + 4)*520;
                #pragma unroll
                for (int g = 0; g < 8; g++) {
                    int n = wn*64 + g*8 + qr;
                    float b[2] = { v0[n], v1[n] };
                    mma8(o[0][g], a[0], b);
                    mma8(o[1][g], a[1], b);
                }
            }
        }
        __syncthreads();   // all Ssp/V reads done before next chunk's issues
    }

    // ---------------- epilogue ----------------
    #pragma unroll
    for (int f = 0; f < 2; f++)
        #pragma unroll
        for (int g = 0; g < 8; g++) {
            int r = i0 + wm*32 + f*16 + qr;
            int c = wn*64 + g*8 + 2*qc;
            *(float2*)&O[(size_t)r*DIM + c]       = make_float2(o[f][g][0], o[f][g][1]);
            *(float2*)&O[(size_t)(r + 8)*DIM + c] = make_float2(o[f][g][2], o[f][g][3]);
        }
}

// ===========================================================================
// Small GEMMs, single-pass tf32: C = act(A @ B + bias).  BM=128, BN=64, BK=32.
// 256 thr, warps 4(m) x 2(n), warp tile 32x32.
// PERM=1: pair-interleave output columns within each 8-group (for Q, K).
// smem: As[128][36] + Bs[32][72] = 6912 fl = 27648 B.
// ===========================================================================
#define GEMM_SMEM 27648

template<int ACT, int ROUND, int PERM>
__global__ void __launch_bounds__(256) gemm_tf32(
    const float* __restrict__ A, const float* __restrict__ B,
    const float* __restrict__ bias, float* __restrict__ C)
{
    extern __shared__ float sm[];
    float (*As)[36] = (float(*)[36]) sm;            // 4608
    float (*Bs)[72] = (float(*)[72])(sm + 4608);    // 2304

    const int tid = threadIdx.x;
    const int lane = tid & 31, w = tid >> 5;
    const int wm = w >> 1, wn = w & 1;
    const int qr = lane >> 2, qc = lane & 3;
    const int bm = blockIdx.x * 128, bn = blockIdx.y * 64;

    float acc[2][4][4];
    #pragma unroll
    for (int f = 0; f < 2; f++)
        #pragma unroll
        for (int g = 0; g < 4; g++)
            #pragma unroll
            for (int e = 0; e < 4; e++) acc[f][g][e] = 0.f;

    float4 ap[4]; float4 bp[2];
    #pragma unroll
    for (int p = 0; p < 4; p++) {
        int idx = tid + p*256, r = idx >> 3, c4 = (idx & 7) * 4;
        ap[p] = *(const float4*)&A[(size_t)(bm + r)*DIM + c4];
    }
    #pragma unroll
    for (int p = 0; p < 2; p++) {
        int idx = tid + p*256, r = idx >> 4, c4 = (idx & 15) * 4;
        bp[p] = *(const float4*)&B[(size_t)r*DIM + bn + c4];
    }

    #pragma unroll 1
    for (int kc = 0; kc < 16; kc++) {
        #pragma unroll
        for (int p = 0; p < 4; p++) {
            int idx = tid + p*256, r = idx >> 3, c4 = (idx & 7) * 4;
            As[r][c4+0] = tf32r(ap[p].x); As[r][c4+1] = tf32r(ap[p].y);
            As[r][c4+2] = tf32r(ap[p].z); As[r][c4+3] = tf32r(ap[p].w);
        }
        #pragma unroll
        for (int p = 0; p < 2; p++) {
            int idx = tid + p*256, r = idx >> 4, c4 = (idx & 15) * 4;
            Bs[r][c4+0] = tf32r(bp[p].x); Bs[r][c4+1] = tf32r(bp[p].y);
            Bs[r][c4+2] = tf32r(bp[p].z); Bs[r][c4+3] = tf32r(bp[p].w);
        }
        __syncthreads();
        if (kc < 15) {
            #pragma unroll
            for (int p = 0; p < 4; p++) {
                int idx = tid + p*256, r = idx >> 3, c4 = (idx & 7) * 4;
                ap[p] = *(const float4*)&A[(size_t)(bm + r)*DIM + (kc+1)*32 + c4];
            }
            #pragma unroll
            for (int p = 0; p < 2; p++) {
                int idx = tid + p*256, r = idx >> 4, c4 = (idx & 15) * 4;
                bp[p] = *(const float4*)&B[(size_t)((kc+1)*32 + r)*DIM + bn + c4];
            }
        }
        #pragma unroll
        for (int k8 = 0; k8 < 4; k8++) {
            const int kk = k8*8 + qc;
            float a[2][4];
            #pragma unroll
            for (int f = 0; f < 2; f++) {
                int rb = wm*32 + f*16 + qr;
                a[f][0] = As[rb][kk];   a[f][1] = As[rb+8][kk];
                a[f][2] = As[rb][kk+4]; a[f][3] = As[rb+8][kk+4];
            }
            #pragma unroll
            for (int g = 0; g < 4; g++) {
                int n = wn*32 + g*8 + qr;
                float b[2] = { Bs[kk][n], Bs[kk+4][n] };
                mma8(acc[0][g], a[0], b);
                mma8(acc[1][g], a[1], b);
            }
        }
        __syncthreads();
    }

    #pragma unroll
    for (int f = 0; f < 2; f++)
        #pragma unroll
        for (int g = 0; g < 4; g++) {
            int r = bm + wm*32 + f*16 + qr;
            int c = bn + wn*32 + g*8 + 2*qc;
            float2 bb = *(const float2*)&bias[c - bn + wn*32*0 + (c & 511) - (c & 511) + c % DIM];
            bb = *(const float2*)&bias[c % DIM];     // bias indexed by logical col
            float v0 = acc[f][g][0] + bb.x, v1 = acc[f][g][1] + bb.y;
            float v2 = acc[f][g][2] + bb.x, v3 = acc[f][g][3] + bb.y;
            if (ACT == 1) {
                v0 = 0.5f*v0*(1.f + erff(v0*0.70710678118654752f));
                v1 = 0.5f*v1*(1.f + erff(v1*0.70710678118654752f));
                v2 = 0.5f*v2*(1.f + erff(v2*0.70710678118654752f));
                v3 = 0.5f*v3*(1.f + erff(v3*0.70710678118654752f));
            }
            if (ROUND == 1) { v0 = tf32r(v0); v1 = tf32r(v1); v2 = tf32r(v2); v3 = tf32r(v3); }
            if (PERM == 1) {
                int m0 = c & 7;            // even: 0,2,4,6
                int m1 = (c + 1) & 7;      // odd:  1,3,5,7
                int p0 = (c & ~7) + ((m0 < 4) ? 2*m0 : 2*(m0-4)+1);
                int p1 = (c & ~7) + ((m1 < 4) ? 2*m1 : 2*(m1-4)+1);
                C[(size_t)r*DIM + p0]       = v0;
                C[(size_t)r*DIM + p1]       = v1;
                C[(size_t)(r + 8)*DIM + p0] = v2;
                C[(size_t)(r + 8)*DIM + p1] = v3;
            } else {
                *(float2*)&C[(size_t)r*DIM + c]       = make_float2(v0, v1);
                *(float2*)&C[(size_t)(r + 8)*DIM + c] = make_float2(v2, v3);
            }
        }
}

// ---------------------------------------------------------------------------
__global__ void groupnorm_kernel(float* __restrict__ out,
                                 const float* __restrict__ gamma,
                                 const float* __restrict__ beta)
{
    __shared__ float buf[512];
    __shared__ float smu[16], siv[16];
    const int row = blockIdx.x;
    const int tid = threadIdx.x;
    float* p = out + (size_t)row * DIM;
    buf[tid]       = p[tid];
    buf[tid + 256] = p[tid + 256];
    __syncthreads();
    if (tid < 16) {
        float sx = 0.f, s2 = 0.f;
        #pragma unroll
        for (int c = 0; c < 32; c++) { float v = buf[tid*32 + c]; sx += v; s2 += v*v; }
        float mu  = sx * (1.f/32.f);
        float var = s2 * (1.f/32.f) - mu*mu;
        smu[tid] = mu;
        siv[tid] = rsqrtf(var + 1e-5f);
    }
    __syncthreads();
    #pragma unroll
    for (int q = 0; q < 2; q++) {
        int c = tid + q*256;
        int g = c >> 5;
        p[c] = (buf[c] - smu[g]) * siv[g] * gamma[c] + beta[c];
    }
}

// ---------------------------------------------------------------------------
extern "C" void kernel_launch(void* const* d_in, const int* in_sizes, int n_in,
                              void* d_out, int out_size)
{
    const float* x     = (const float*)d_in[0];
    const float* D     = (const float*)d_in[1];
    const float* Wq    = (const float*)d_in[2];
    const float* bq    = (const float*)d_in[3];
    const float* Wk    = (const float*)d_in[4];
    const float* bk    = (const float*)d_in[5];
    const float* Wv    = (const float*)d_in[6];
    const float* bv    = (const float*)d_in[7];
    const float* Wf    = (const float*)d_in[8];
    const float* bf    = (const float*)d_in[9];
    const float* Wp    = (const float*)d_in[10];
    const float* bp    = (const float*)d_in[11];
    const float* gamma = (const float*)d_in[12];
    const float* beta  = (const float*)d_in[13];
    float* out = (float*)d_out;

    float *Q, *K, *V, *XR, *H;
    cudaGetSymbolAddress((void**)&Q,  g_Q);
    cudaGetSymbolAddress((void**)&K,  g_K);
    cudaGetSymbolAddress((void**)&V,  g_V);
    cudaGetSymbolAddress((void**)&XR, g_XR);
    cudaGetSymbolAddress((void**)&H,  g_H);

    cudaFuncSetAttribute(gemm_tf32<0,1,1>,
                         cudaFuncAttributeMaxDynamicSharedMemorySize, GEMM_SMEM);
    cudaFuncSetAttribute(gemm_tf32<0,1,0>,
                         cudaFuncAttributeMaxDynamicSharedMemorySize, GEMM_SMEM);
    cudaFuncSetAttribute(gemm_tf32<1,0,0>,
                         cudaFuncAttributeMaxDynamicSharedMemorySize, GEMM_SMEM);
    cudaFuncSetAttribute(gemm_tf32<0,0,0>,
                         cudaFuncAttributeMaxDynamicSharedMemorySize, GEMM_SMEM);
    cudaFuncSetAttribute(retention_mma,
                         cudaFuncAttributeMaxDynamicSharedMemorySize, RET_SMEM);

    dim3 gs(NROWS/128, DIM/64);    // 64 x 8
    gemm_tf32<0,1,1><<<gs, 256, GEMM_SMEM>>>(x, Wq, bq, Q);   // Q: permuted cols
    gemm_tf32<0,1,1><<<gs, 256, GEMM_SMEM>>>(x, Wk, bk, K);   // K: permuted cols
    gemm_tf32<0,1,0><<<gs, 256, GEMM_SMEM>>>(x, Wv, bv, V);   // V: normal

    retention_mma<<<NROWS/64, 512, RET_SMEM>>>(Q, K, V, D, XR);

    gemm_tf32<1,0,0><<<gs, 256, GEMM_SMEM>>>(XR, Wf, bf, H);  // exact GELU
    gemm_tf32<0,0,0><<<gs, 256, GEMM_SMEM>>>(H,  Wp, bp, out);

    groupnorm_kernel<<<NROWS, 256>>>(out, gamma, beta);
}